// round 8
// baseline (speedup 1.0000x reference)
#include <cuda_runtime.h>
#include <cuda_bf16.h>
#include <stdint.h>
#include <math.h>

#define B_   32
#define C_   256
#define HH   56
#define WW   56
#define E_   4
#define O_   256
#define HID_ 64
#define NPIX 3136
#define KDIM 2304
#define WPERB (O_*KDIM)
#define BK   32
#define NKT  (KDIM/BK)                // 72 k-tiles
#define MT   128
#define NTL  128

// ---------------- device scratch (no runtime allocation) ----------------
__device__ float g_routing[B_*E_];
__device__ float g_pooled[B_*C_];
// fragment-packed tf32 weights: [b][tile_m(2)][kt(72)][block(32)][offs16(32)][4]
__device__ __align__(16) float g_combined[(size_t)B_*WPERB];

// ---------------- helpers ----------------
__device__ __forceinline__ uint32_t f2tf32(float f) {
    uint32_t u;
    asm("cvt.rna.tf32.f32 %0, %1;" : "=r"(u) : "f"(f));
    return u;
}

__device__ __forceinline__ void mma_tf32s(float* d,
                                          uint32_t a0, uint32_t a1, uint32_t a2, uint32_t a3,
                                          uint32_t b0, uint32_t b1) {
    asm volatile(
        "mma.sync.aligned.m16n8k8.row.col.f32.tf32.tf32.f32 "
        "{%0,%1,%2,%3}, {%4,%5,%6,%7}, {%8,%9}, {%0,%1,%2,%3};"
        : "+f"(d[0]), "+f"(d[1]), "+f"(d[2]), "+f"(d[3])
        : "r"(a0), "r"(a1), "r"(a2), "r"(a3), "r"(b0), "r"(b1));
}

#define CP_ASYNC16(dst_u32, src_ptr) \
    asm volatile("cp.async.cg.shared.global [%0], [%1], 16;" :: "r"(dst_u32), "l"(src_ptr))
#define CP_COMMIT() asm volatile("cp.async.commit_group;" ::: "memory")
#define CP_WAIT0()  asm volatile("cp.async.wait_group 0;"  ::: "memory")

// ===========================================================================
// Kernel 1a: per-channel global average pool. grid (C_, B_), 128 threads.
// ===========================================================================
__global__ void __launch_bounds__(128) pool_kernel(const float* __restrict__ x) {
    const int c = blockIdx.x, b = blockIdx.y;
    const int tid = threadIdx.x;
    const float4* xc = (const float4*)(x + ((size_t)b*C_ + c)*NPIX);
    float s = 0.f;
    for (int i = tid; i < NPIX/4; i += 128) { float4 v = xc[i]; s += (v.x+v.y)+(v.z+v.w); }
    #pragma unroll
    for (int o = 16; o; o >>= 1) s += __shfl_xor_sync(0xffffffffu, s, o);
    __shared__ float ws[4];
    if ((tid & 31) == 0) ws[tid >> 5] = s;
    __syncthreads();
    if (tid == 0) g_pooled[b*C_ + c] = (ws[0]+ws[1]+ws[2]+ws[3]) * (1.0f/(float)NPIX);
}

// ===========================================================================
// Kernel 1b: MLP + softmax routing. grid B_, 64 threads.
// ===========================================================================
__global__ void __launch_bounds__(64) mlp_kernel(const float* __restrict__ rw1,
                                                 const float* __restrict__ rb1,
                                                 const float* __restrict__ rw2,
                                                 const float* __restrict__ rb2) {
    const int b = blockIdx.x, t = threadIdx.x;
    __shared__ float pl[C_];
    __shared__ float hid[HID_];
    __shared__ float logits[E_];
    for (int c = t; c < C_; c += 64) pl[c] = g_pooled[b*C_ + c];
    __syncthreads();
    {
        float s = rb1[t];
        const float* w = rw1 + t * C_;
        #pragma unroll 8
        for (int c = 0; c < C_; c++) s = fmaf(w[c], pl[c], s);
        hid[t] = fmaxf(s, 0.f);
    }
    __syncthreads();
    if (t < E_) {
        float s = rb2[t];
        const float* w = rw2 + t * HID_;
        #pragma unroll 8
        for (int h = 0; h < HID_; h++) s = fmaf(w[h], hid[h], s);
        logits[t] = s;
    }
    __syncthreads();
    if (t == 0) {
        float m = logits[0];
        #pragma unroll
        for (int e = 1; e < E_; e++) m = fmaxf(m, logits[e]);
        float ex[E_], sum = 0.f;
        #pragma unroll
        for (int e = 0; e < E_; e++) { ex[e] = expf(logits[e] - m); sum += ex[e]; }
        float inv = 1.0f / sum;
        #pragma unroll
        for (int e = 0; e < E_; e++) g_routing[b*E_ + e] = ex[e] * inv;
    }
}

// ===========================================================================
// Kernel 2: mix experts -> fragment-packed tf32 weights.
//   Packed float4 id v (0..147455 per sample):
//     T = v>>10 (tile_m*72+kt), q = v&1023, blk = q>>5, offs = q&31
//     g = offs>>2, tg = (offs&3) ^ ((g>>1)&3)
//     mi = blk>>2, rowsel = (blk>>1)&1, h = blk&1
//     o = tile_m*128 + mi*16 + rowsel*8 + g
//     k(jj) = kt*32 + h*16 + tg + 4*jj
// ===========================================================================
__global__ void __launch_bounds__(256) combine_kernel(const float* __restrict__ experts) {
    const int b = blockIdx.y;
    const int v = blockIdx.x * 256 + threadIdx.x;       // 0 .. 147455
    const int T = v >> 10;
    const int q = v & 1023;
    const int kt = T % NKT;
    const int tile_m = T / NKT;
    const int blk = q >> 5;
    const int offs = q & 31;
    const int g  = offs >> 2;
    const int tg = (offs & 3) ^ ((g >> 1) & 3);
    const int mi = blk >> 2;
    const int rowsel = (blk >> 1) & 1;
    const int h = blk & 1;
    const int o = tile_m*128 + mi*16 + rowsel*8 + g;
    const int kbase = kt*32 + h*16 + tg;

    const float r0 = g_routing[b*E_+0], r1 = g_routing[b*E_+1];
    const float r2 = g_routing[b*E_+2], r3 = g_routing[b*E_+3];

    uint4 ov;
    uint32_t* op = (uint32_t*)&ov;
    #pragma unroll
    for (int jj = 0; jj < 4; jj++) {
        const size_t off = (size_t)o*KDIM + kbase + 4*jj;
        float s = r0*__ldg(experts + off)
                + r1*__ldg(experts + (size_t)WPERB   + off)
                + r2*__ldg(experts + (size_t)2*WPERB + off)
                + r3*__ldg(experts + (size_t)3*WPERB + off);
        op[jj] = f2tf32(s);
    }
    ((uint4*)g_combined)[(size_t)b*147456 + v] = ov;
}

// ===========================================================================
// Kernel 3: TF32 mma.sync implicit-GEMM conv, fragment-packed LDS.128.
//   CTA 128x128, 8 warps = 2(m) x 4(n), warp tile 64x32, 2 CTAs/SM.
//   smem (float4 units): A stages [0,2048), B stages [2048,4096), ktab after.
// ===========================================================================
__global__ void __launch_bounds__(256, 2) conv_mma_kernel(const float* __restrict__ x,
                                                          float* __restrict__ out) {
    extern __shared__ float sm[];
    uint4* smv = (uint4*)sm;
    int*   ktab = (int*)(sm + 16384);          // 2304 ints

    const int tid    = threadIdx.x;
    const int lane   = tid & 31;
    const int warp   = tid >> 5;
    const int nBase  = blockIdx.x * NTL;
    const int tile_m = blockIdx.y;
    const int b      = blockIdx.z;

    const int g  = lane >> 2;
    const int tg = lane & 3;
    const int wm = warp >> 2;      // 0..1 (m)
    const int wn = warp & 3;       // 0..3 (n)
    const int offs16 = g*4 + (tg ^ ((g >> 1) & 3));

    // packed im2col table: (gmem offset << 4) | tap
    for (int k = tid; k < KDIM; k += 256) {
        int c = k / 9, rem = k - 9*c;
        int ky = rem / 3 - 1, kx = rem % 3 - 1;
        ktab[k] = ((c*NPIX + ky*WW + kx) << 4) | ((ky+1)*3 + (kx+1));
    }
    __syncthreads();

    const float* Asrc0 = g_combined + (size_t)b*WPERB + (size_t)tile_m*NKT*4096;
    const float* xb    = x + (size_t)b * C_ * NPIX;

    // B producer: pixel nl, k-half kh
    const int nl = tid & 127;
    const int kh = tid >> 7;
    const int n  = nBase + nl;
    const int ny = n / WW, nx = n - (n / WW) * WW;
    const int g2 = nl & 7;

    uint32_t vmask = 0;
    if (n < NPIX) {
        #pragma unroll
        for (int dy = -1; dy <= 1; dy++)
            #pragma unroll
            for (int dx = -1; dx <= 1; dx++)
                if ((unsigned)(ny+dy) < 56u && (unsigned)(nx+dx) < 56u)
                    vmask |= 1u << ((dy+1)*3 + (dx+1));
    }

    const uint32_t as_u32 = (uint32_t)__cvta_generic_to_shared(sm);

    uint32_t breg[16];

    #define ISSUE_A(kt_, s) do {                                                     \
        const float* _src = Asrc0 + (size_t)(kt_)*4096;                              \
        _Pragma("unroll")                                                            \
        for (int i = 0; i < 4; i++) {                                                \
            int c = tid + i*256;                                                     \
            CP_ASYNC16(as_u32 + ((s)*1024 + c)*16u, _src + c*4);                     \
        }                                                                            \
        CP_COMMIT();                                                                 \
    } while (0)

    #define LDG_B(kt_) do {                                                          \
        const int4* _kt4 = (const int4*)(ktab + (kt_)*BK + kh*16);                   \
        _Pragma("unroll")                                                            \
        for (int qq = 0; qq < 4; qq++) {                                             \
            int4 kv = _kt4[qq];                                                      \
            int vv0 = kv.x, vv1 = kv.y, vv2 = kv.z, vv3 = kv.w;                      \
            float f0=0.f,f1=0.f,f2=0.f,f3=0.f;                                       \
            if ((vmask >> (vv0 & 15)) & 1u) f0 = __ldg(xb + (vv0 >> 4) + n);         \
            if ((vmask >> (vv1 & 15)) & 1u) f1 = __ldg(xb + (vv1 >> 4) + n);         \
            if ((vmask >> (vv2 & 15)) & 1u) f2 = __ldg(xb + (vv2 >> 4) + n);         \
            if ((vmask >> (vv3 & 15)) & 1u) f3 = __ldg(xb + (vv3 >> 4) + n);         \
            breg[qq*4+0] = f2tf32(f0); breg[qq*4+1] = f2tf32(f1);                    \
            breg[qq*4+2] = f2tf32(f2); breg[qq*4+3] = f2tf32(f3);                    \
        }                                                                            \
    } while (0)

    // B fragment-order STS: block = (nl>>3)*2 + kh; float4 per tgv:
    //   offs = g2*4 + (tgv ^ ((g2>>1)&3)); value = {breg[tgv], breg[tgv+4], ...}
    #define STS_B(s) do {                                                            \
        uint4* _d = smv + 2048 + (s)*1024 + ((nl >> 3)*2 + kh)*32 + g2*4;            \
        const int _sw = (g2 >> 1) & 3;                                               \
        _Pragma("unroll")                                                            \
        for (int tgv = 0; tgv < 4; tgv++)                                            \
            _d[tgv ^ _sw] = make_uint4(breg[tgv], breg[tgv+4],                       \
                                       breg[tgv+8], breg[tgv+12]);                   \
    } while (0)

    #define COMPUTE_H(h_, curB) do {                                                 \
        uint4 va0[4], va1[4];                                                        \
        _Pragma("unroll")                                                            \
        for (int mi = 0; mi < 4; mi++) {                                             \
            const int blk = ((wm*4 + mi)*4 + (h_))*32;                               \
            va0[mi] = smv[(curB) + blk + offs16];                                    \
            va1[mi] = smv[(curB) + blk + 64 + offs16];                               \
        }                                                                            \
        _Pragma("unroll")                                                            \
        for (int ni = 0; ni < 4; ni++) {                                             \
            uint4 vb = smv[2048 + (curB) + ((wn*4 + ni)*2 + (h_))*32 + offs16];      \
            _Pragma("unroll")                                                        \
            for (int mi = 0; mi < 4; mi++) {                                         \
                mma_tf32s(acc[mi][ni], va0[mi].x, va1[mi].x, va0[mi].y, va1[mi].y,   \
                          vb.x, vb.y);                                               \
                mma_tf32s(acc[mi][ni], va0[mi].z, va1[mi].z, va0[mi].w, va1[mi].w,   \
                          vb.z, vb.w);                                               \
            }                                                                        \
        }                                                                            \
    } while (0)

    float acc[4][4][4];
    #pragma unroll
    for (int mi = 0; mi < 4; mi++)
        #pragma unroll
        for (int ni = 0; ni < 4; ni++)
            #pragma unroll
            for (int qq = 0; qq < 4; qq++) acc[mi][ni][qq] = 0.f;

    // ---- prologue ----
    ISSUE_A(0, 0);
    LDG_B(0);
    STS_B(0);
    CP_WAIT0();
    __syncthreads();

    for (int kt = 0; kt < NKT; kt++) {
        const int cur = kt & 1;
        const int curB = cur * 1024;
        if (kt + 1 < NKT) {
            ISSUE_A(kt + 1, cur ^ 1);
            LDG_B(kt + 1);
        }

        COMPUTE_H(0, curB);

        if (kt + 1 < NKT) STS_B(cur ^ 1);   // that buffer idle since barrier kt-1

        COMPUTE_H(1, curB);

        if (kt + 1 < NKT) {
            CP_WAIT0();
            __syncthreads();
        }
    }

    // ---- epilogue ----
    float* ob = out + (size_t)b * O_ * NPIX;
    #pragma unroll
    for (int mi = 0; mi < 4; mi++) {
        const int r0 = tile_m*128 + wm*64 + mi*16 + g;
        #pragma unroll
        for (int ni = 0; ni < 4; ni++) {
            const int cb = nBase + wn*32 + ni*8 + 2*tg;
            if (cb < NPIX) {
                *(float2*)(ob + (size_t)r0*NPIX + cb)     = make_float2(acc[mi][ni][0], acc[mi][ni][1]);
                *(float2*)(ob + (size_t)(r0+8)*NPIX + cb) = make_float2(acc[mi][ni][2], acc[mi][ni][3]);
            }
        }
    }
    #undef ISSUE_A
    #undef LDG_B
    #undef STS_B
    #undef COMPUTE_H
}

#define CONV_SMEM (16384*4 + KDIM*4)   // 65536 + 9216 = 74752 B

// ===========================================================================
extern "C" void kernel_launch(void* const* d_in, const int* in_sizes, int n_in,
                              void* d_out, int out_size) {
    const float* x       = (const float*)d_in[0];
    const float* experts = (const float*)d_in[1];
    const float* rw1     = (const float*)d_in[2];
    const float* rb1     = (const float*)d_in[3];
    const float* rw2     = (const float*)d_in[4];
    const float* rb2     = (const float*)d_in[5];
    float* out           = (float*)d_out;

    static bool attr_set = false;
    if (!attr_set) {
        cudaFuncSetAttribute(conv_mma_kernel,
                             cudaFuncAttributeMaxDynamicSharedMemorySize, CONV_SMEM);
        attr_set = true;
    }

    pool_kernel<<<dim3(C_, B_), 128>>>(x);
    mlp_kernel<<<B_, 64>>>(rw1, rb1, rw2, rb2);
    combine_kernel<<<dim3(576, B_), 256>>>(experts);
    conv_mma_kernel<<<dim3(25, 2, B_), 256, CONV_SMEM>>>(x, out);
}

// round 9
// speedup vs baseline: 1.0276x; 1.0276x over previous
#include <cuda_runtime.h>
#include <cuda_bf16.h>
#include <stdint.h>
#include <math.h>

#define B_   32
#define C_   256
#define HH   56
#define WW   56
#define E_   4
#define O_   256
#define HID_ 64
#define NPIX 3136
#define KDIM 2304
#define WPERB (O_*KDIM)
#define BK   32
#define NKT  (KDIM/BK)                // 72 k-tiles
#define PADK 36                       // B smem k-stride (floats)

// ---------------- device scratch (no runtime allocation) ----------------
__device__ float g_routing[B_*E_];
__device__ float g_pooled[B_*C_];
// A fragment-packed tf32: [b][tile_m(2)*NKT + kt][blk(32)][lane(32)] as uint4
//   blk = mi8*4 + rowsel*2 + h ; lane = g*4+tg
//   uint4 = W[m][16h+tg + {0,4,8,12}],  m = tile_m*128 + mi8*16 + rowsel*8 + g
__device__ __align__(16) float g_combined[(size_t)B_*WPERB];

// ---------------- helpers ----------------
__device__ __forceinline__ uint32_t f2tf32(float f) {
    uint32_t u;
    asm("cvt.rna.tf32.f32 %0, %1;" : "=r"(u) : "f"(f));
    return u;
}

__device__ __forceinline__ void mma_tf32s(float* d,
                                          uint32_t a0, uint32_t a1, uint32_t a2, uint32_t a3,
                                          uint32_t b0, uint32_t b1) {
    asm volatile(
        "mma.sync.aligned.m16n8k8.row.col.f32.tf32.tf32.f32 "
        "{%0,%1,%2,%3}, {%4,%5,%6,%7}, {%8,%9}, {%0,%1,%2,%3};"
        : "+f"(d[0]), "+f"(d[1]), "+f"(d[2]), "+f"(d[3])
        : "r"(a0), "r"(a1), "r"(a2), "r"(a3), "r"(b0), "r"(b1));
}

#define CP_ASYNC16(dst_u32, src_ptr) \
    asm volatile("cp.async.cg.shared.global [%0], [%1], 16;" :: "r"(dst_u32), "l"(src_ptr))
#define CP_COMMIT() asm volatile("cp.async.commit_group;" ::: "memory")
#define CP_WAIT0()  asm volatile("cp.async.wait_group 0;"  ::: "memory")

// ===========================================================================
// Kernel 1a: per-channel global average pool. grid (C_, B_), 128 threads.
// ===========================================================================
__global__ void __launch_bounds__(128) pool_kernel(const float* __restrict__ x) {
    const int c = blockIdx.x, b = blockIdx.y;
    const int tid = threadIdx.x;
    const float4* xc = (const float4*)(x + ((size_t)b*C_ + c)*NPIX);
    float s = 0.f;
    for (int i = tid; i < NPIX/4; i += 128) { float4 v = xc[i]; s += (v.x+v.y)+(v.z+v.w); }
    #pragma unroll
    for (int o = 16; o; o >>= 1) s += __shfl_xor_sync(0xffffffffu, s, o);
    __shared__ float ws[4];
    if ((tid & 31) == 0) ws[tid >> 5] = s;
    __syncthreads();
    if (tid == 0) g_pooled[b*C_ + c] = (ws[0]+ws[1]+ws[2]+ws[3]) * (1.0f/(float)NPIX);
}

// ===========================================================================
// Kernel 1b: MLP + softmax routing. grid B_, 64 threads.
// ===========================================================================
__global__ void __launch_bounds__(64) mlp_kernel(const float* __restrict__ rw1,
                                                 const float* __restrict__ rb1,
                                                 const float* __restrict__ rw2,
                                                 const float* __restrict__ rb2) {
    const int b = blockIdx.x, t = threadIdx.x;
    __shared__ float pl[C_];
    __shared__ float hid[HID_];
    __shared__ float logits[E_];
    for (int c = t; c < C_; c += 64) pl[c] = g_pooled[b*C_ + c];
    __syncthreads();
    {
        float s = rb1[t];
        const float* w = rw1 + t * C_;
        #pragma unroll 8
        for (int c = 0; c < C_; c++) s = fmaf(w[c], pl[c], s);
        hid[t] = fmaxf(s, 0.f);
    }
    __syncthreads();
    if (t < E_) {
        float s = rb2[t];
        const float* w = rw2 + t * HID_;
        #pragma unroll 8
        for (int h = 0; h < HID_; h++) s = fmaf(w[h], hid[h], s);
        logits[t] = s;
    }
    __syncthreads();
    if (t == 0) {
        float m = logits[0];
        #pragma unroll
        for (int e = 1; e < E_; e++) m = fmaxf(m, logits[e]);
        float ex[E_], sum = 0.f;
        #pragma unroll
        for (int e = 0; e < E_; e++) { ex[e] = expf(logits[e] - m); sum += ex[e]; }
        float inv = 1.0f / sum;
        #pragma unroll
        for (int e = 0; e < E_; e++) g_routing[b*E_ + e] = ex[e] * inv;
    }
}

// ===========================================================================
// Kernel 2: mix experts -> A fragment-packed tf32 weights, smem-staged.
//   grid (2*NKT, B_) = (144, 32), 256 threads.
//   Coalesced source reads, coalesced packed writes.
// ===========================================================================
__global__ void __launch_bounds__(256) combine_kernel(const float* __restrict__ experts) {
    __shared__ float st[128*33];
    const int b  = blockIdx.y;
    const int bx = blockIdx.x;                 // tile_m*NKT + kt
    const int tile_m = bx / NKT;
    const int kt = bx - tile_m*NKT;
    const int tid = threadIdx.x;

    const float r0 = g_routing[b*E_+0], r1 = g_routing[b*E_+1];
    const float r2 = g_routing[b*E_+2], r3 = g_routing[b*E_+3];

    // read 128 rows x 32 k (mixed, tf32-rounded) into smem
    const int row = tid >> 1, seg = tid & 1;
    const size_t base = (size_t)(tile_m*128 + row)*KDIM + kt*32 + seg*16;
    #pragma unroll
    for (int q = 0; q < 4; q++) {
        float4 a = *(const float4*)(experts + base + 4*q);
        float4 c = *(const float4*)(experts + (size_t)WPERB   + base + 4*q);
        float4 d = *(const float4*)(experts + (size_t)2*WPERB + base + 4*q);
        float4 f = *(const float4*)(experts + (size_t)3*WPERB + base + 4*q);
        float* dst = st + row*33 + seg*16 + 4*q;
        dst[0] = __uint_as_float(f2tf32(r0*a.x + r1*c.x + r2*d.x + r3*f.x));
        dst[1] = __uint_as_float(f2tf32(r0*a.y + r1*c.y + r2*d.y + r3*f.y));
        dst[2] = __uint_as_float(f2tf32(r0*a.z + r1*c.z + r2*d.z + r3*f.z));
        dst[3] = __uint_as_float(f2tf32(r0*a.w + r1*c.w + r2*d.w + r3*f.w));
    }
    __syncthreads();

    // write fragment-packed (coalesced uint4)
    uint4* gout = (uint4*)g_combined + (size_t)b*147456 + (size_t)bx*1024;
    #pragma unroll
    for (int w = 0; w < 4; w++) {
        const int u    = tid + 256*w;          // 0..1023
        const int blkI = u >> 5, offs = u & 31;
        const int gi   = offs >> 2, tgi = offs & 3;
        const int mi8  = blkI >> 2, rowsel = (blkI >> 1) & 1, h = blkI & 1;
        const float* s = st + (mi8*16 + rowsel*8 + gi)*33 + h*16 + tgi;
        gout[u] = make_uint4(__float_as_uint(s[0]), __float_as_uint(s[4]),
                             __float_as_uint(s[8]), __float_as_uint(s[12]));
    }
}

// ===========================================================================
// Kernel 3: TF32 mma.sync implicit-GEMM conv.
//   CTA 128(oc) x 128(px), 8 warps = 2(m) x 4(n), warp tile 64x32, 2 CTAs/SM.
//   A: fragment-packed gmem -> linear cp.async -> uint4 frag LDS.
//   B: im2col LDG -> STS.128 -> conflict-free scalar frag LDS (PADK=36).
// smem floats: A [0,8192) (2 x 1024 uint4), B [8192,17408), ktab [17408,19712)
// ===========================================================================
__global__ void __launch_bounds__(256, 2) conv_mma_kernel(const float* __restrict__ x,
                                                          float* __restrict__ out) {
    extern __shared__ float sm[];
    uint4* Apk  = (uint4*)sm;
    float* Bs   = sm + 8192;
    int*   ktab = (int*)(sm + 17408);

    const int tid    = threadIdx.x;
    const int lane   = tid & 31;
    const int warp   = tid >> 5;
    const int nBase  = blockIdx.x * 128;
    const int tile_m = blockIdx.y;
    const int b      = blockIdx.z;

    const int g  = lane >> 2;
    const int tg = lane & 3;
    const int wm = warp >> 2;      // 0..1 (m)
    const int wn = warp & 3;       // 0..3 (n)

    // packed im2col table: (gmem offset << 4) | tap
    for (int k = tid; k < KDIM; k += 256) {
        int c = k / 9, rem = k - 9*c;
        int ky = rem / 3 - 1, kx = rem % 3 - 1;
        ktab[k] = ((c*NPIX + ky*WW + kx) << 4) | ((ky+1)*3 + (kx+1));
    }
    __syncthreads();

    const float* Asrc0 = g_combined + (size_t)b*WPERB + (size_t)(tile_m*NKT)*4096;
    const float* xb    = x + (size_t)b * C_ * NPIX;

    // B producer coords
    const int nl = tid & 127;
    const int kh = tid >> 7;
    const int n  = nBase + nl;
    const int ny = n / WW, nx = n - (n / WW) * WW;

    uint32_t vmask = 0;
    if (n < NPIX) {
        #pragma unroll
        for (int dy = -1; dy <= 1; dy++)
            #pragma unroll
            for (int dx = -1; dx <= 1; dx++)
                if ((unsigned)(ny+dy) < 56u && (unsigned)(nx+dx) < 56u)
                    vmask |= 1u << ((dy+1)*3 + (dx+1));
    }

    const uint32_t as_u32 = (uint32_t)__cvta_generic_to_shared(sm);

    uint32_t breg[16];

    #define ISSUE_A(kt_, s) do {                                                     \
        const float* _src = Asrc0 + (size_t)(kt_)*4096;                              \
        _Pragma("unroll")                                                            \
        for (int i = 0; i < 4; i++) {                                                \
            int c = tid + i*256;                                                     \
            CP_ASYNC16(as_u32 + ((s)*1024 + c)*16u, _src + c*4);                     \
        }                                                                            \
        CP_COMMIT();                                                                 \
    } while (0)

    #define LDG_B(kt_) do {                                                          \
        const int4* _kt4 = (const int4*)(ktab + (kt_)*BK + kh*16);                   \
        _Pragma("unroll")                                                            \
        for (int qq = 0; qq < 4; qq++) {                                             \
            int4 kv = _kt4[qq];                                                      \
            float f0=0.f,f1=0.f,f2=0.f,f3=0.f;                                       \
            if ((vmask >> (kv.x & 15)) & 1u) f0 = __ldg(xb + (kv.x >> 4) + n);       \
            if ((vmask >> (kv.y & 15)) & 1u) f1 = __ldg(xb + (kv.y >> 4) + n);       \
            if ((vmask >> (kv.z & 15)) & 1u) f2 = __ldg(xb + (kv.z >> 4) + n);       \
            if ((vmask >> (kv.w & 15)) & 1u) f3 = __ldg(xb + (kv.w >> 4) + n);       \
            breg[qq*4+0] = f2tf32(f0); breg[qq*4+1] = f2tf32(f1);                    \
            breg[qq*4+2] = f2tf32(f2); breg[qq*4+3] = f2tf32(f3);                    \
        }                                                                            \
    } while (0)

    #define STS_B(s) do {                                                            \
        uint4* _d = (uint4*)(Bs + (s)*4608 + nl*PADK + kh*16);                       \
        _Pragma("unroll")                                                            \
        for (int i = 0; i < 4; i++)                                                  \
            _d[i] = make_uint4(breg[i*4], breg[i*4+1], breg[i*4+2], breg[i*4+3]);    \
    } while (0)

    // one k-half (16 k = 2 mma k-steps). B frags first (16 regs), then per-mi A.
    #define COMPUTE_H(h_, cur) do {                                                  \
        const uint32_t* _bw = (const uint32_t*)(Bs + (cur)*4608                      \
                              + (wn*32 + g)*PADK + (h_)*16 + tg);                    \
        uint32_t bf[4][4];                                                           \
        _Pragma("unroll")                                                            \
        for (int ni = 0; ni < 4; ni++) {                                             \
            const uint32_t* _q = _bw + ni*8*PADK;                                    \
            bf[ni][0] = _q[0]; bf[ni][1] = _q[4];                                    \
            bf[ni][2] = _q[8]; bf[ni][3] = _q[12];                                   \
        }                                                                            \
        const uint4* _aw = Apk + (cur)*1024 + lane;                                  \
        _Pragma("unroll")                                                            \
        for (int mi = 0; mi < 4; mi++) {                                             \
            const int _mb = ((wm*4 + mi)*4 + (h_))*32;                               \
            uint4 va0 = _aw[_mb];                                                    \
            uint4 va1 = _aw[_mb + 64];                                               \
            _Pragma("unroll")                                                        \
            for (int ni = 0; ni < 4; ni++) {                                         \
                mma_tf32s(acc[mi][ni], va0.x, va1.x, va0.y, va1.y,                   \
                          bf[ni][0], bf[ni][1]);                                     \
                mma_tf32s(acc[mi][ni], va0.z, va1.z, va0.w, va1.w,                   \
                          bf[ni][2], bf[ni][3]);                                     \
            }                                                                        \
        }                                                                            \
    } while (0)

    float acc[4][4][4];
    #pragma unroll
    for (int mi = 0; mi < 4; mi++)
        #pragma unroll
        for (int ni = 0; ni < 4; ni++)
            #pragma unroll
            for (int qq = 0; qq < 4; qq++) acc[mi][ni][qq] = 0.f;

    // ---- prologue ----
    ISSUE_A(0, 0);
    LDG_B(0);
    STS_B(0);
    CP_WAIT0();
    __syncthreads();

    for (int kt = 0; kt < NKT; kt++) {
        const int cur = kt & 1;
        if (kt + 1 < NKT) {
            ISSUE_A(kt + 1, cur ^ 1);
            LDG_B(kt + 1);
        }

        COMPUTE_H(0, cur);

        if (kt + 1 < NKT) STS_B(cur ^ 1);   // that buffer idle since barrier kt-1

        COMPUTE_H(1, cur);

        if (kt + 1 < NKT) {
            CP_WAIT0();
            __syncthreads();
        }
    }

    // ---- epilogue ----
    float* ob = out + (size_t)b * O_ * NPIX;
    #pragma unroll
    for (int mi = 0; mi < 4; mi++) {
        const int r0 = tile_m*128 + wm*64 + mi*16 + g;
        #pragma unroll
        for (int ni = 0; ni < 4; ni++) {
            const int cb = nBase + wn*32 + ni*8 + 2*tg;
            if (cb < NPIX) {
                *(float2*)(ob + (size_t)r0*NPIX + cb)     = make_float2(acc[mi][ni][0], acc[mi][ni][1]);
                *(float2*)(ob + (size_t)(r0+8)*NPIX + cb) = make_float2(acc[mi][ni][2], acc[mi][ni][3]);
            }
        }
    }
    #undef ISSUE_A
    #undef LDG_B
    #undef STS_B
    #undef COMPUTE_H
}

#define CONV_SMEM (19712*4)   // 78848 B

// ===========================================================================
extern "C" void kernel_launch(void* const* d_in, const int* in_sizes, int n_in,
                              void* d_out, int out_size) {
    const float* x       = (const float*)d_in[0];
    const float* experts = (const float*)d_in[1];
    const float* rw1     = (const float*)d_in[2];
    const float* rb1     = (const float*)d_in[3];
    const float* rw2     = (const float*)d_in[4];
    const float* rb2     = (const float*)d_in[5];
    float* out           = (float*)d_out;

    static bool attr_set = false;
    if (!attr_set) {
        cudaFuncSetAttribute(conv_mma_kernel,
                             cudaFuncAttributeMaxDynamicSharedMemorySize, CONV_SMEM);
        attr_set = true;
    }

    pool_kernel<<<dim3(C_, B_), 128>>>(x);
    mlp_kernel<<<B_, 64>>>(rw1, rb1, rw2, rb2);
    combine_kernel<<<dim3(2*NKT, B_), 256>>>(experts);
    conv_mma_kernel<<<dim3(25, 2, B_), 256, CONV_SMEM>>>(x, out);
}

// round 10
// speedup vs baseline: 1.1708x; 1.1393x over previous
#include <cuda_runtime.h>
#include <cuda_bf16.h>
#include <stdint.h>
#include <math.h>

#define B_   32
#define C_   256
#define HH   56
#define WW   56
#define E_   4
#define O_   256
#define HID_ 64
#define NPIX 3136
#define KDIM 2304
#define WPERB (O_*KDIM)
#define BK   32
#define NKT  (KDIM/BK)                // 72 k-tiles
#define PAD  40                       // smem k-stride (floats), LDS.64 conflict-free

// smem float offsets (conv kernel)
#define ASTG 5120                     // 128*40 floats per A stage
#define BSTG 5120                     // 128*40 floats per B stage
#define BOFF 10240                    // B region start (floats)
#define KOFF 20480                    // ktab start (floats)
#define CONV_SMEM ((KOFF + KDIM)*4)   // 91136 B

// ---------------- device scratch (no runtime allocation) ----------------
__device__ float g_routing[B_*E_];
__device__ float g_pooled[B_*C_];
// A tf32, k-pair interleaved: per (b, tile_m*NKT+kt): 128 rows x 32 cols',
//   col' = ks*8 + pos, pos=(j&3)*2+(j>>2), orig k = kt*32 + ks*8 + j
__device__ __align__(16) float g_combined[(size_t)B_*WPERB];

// ---------------- helpers ----------------
__device__ __forceinline__ uint32_t f2tf32(float f) {
    uint32_t u;
    asm("cvt.rna.tf32.f32 %0, %1;" : "=r"(u) : "f"(f));
    return u;
}
__device__ __forceinline__ uint2 lds64(uint32_t addr) {
    uint2 r;
    asm volatile("ld.shared.v2.u32 {%0,%1}, [%2];" : "=r"(r.x), "=r"(r.y) : "r"(addr));
    return r;
}
__device__ __forceinline__ void sts128(uint32_t addr, uint32_t a, uint32_t b,
                                       uint32_t c, uint32_t d) {
    asm volatile("st.shared.v4.u32 [%0], {%1,%2,%3,%4};"
                 :: "r"(addr), "r"(a), "r"(b), "r"(c), "r"(d) : "memory");
}
__device__ __forceinline__ void mma_tf32s(float* d,
                                          uint32_t a0, uint32_t a1, uint32_t a2, uint32_t a3,
                                          uint32_t b0, uint32_t b1) {
    asm volatile(
        "mma.sync.aligned.m16n8k8.row.col.f32.tf32.tf32.f32 "
        "{%0,%1,%2,%3}, {%4,%5,%6,%7}, {%8,%9}, {%0,%1,%2,%3};"
        : "+f"(d[0]), "+f"(d[1]), "+f"(d[2]), "+f"(d[3])
        : "r"(a0), "r"(a1), "r"(a2), "r"(a3), "r"(b0), "r"(b1));
}

#define CP_ASYNC16(dst_u32, src_ptr) \
    asm volatile("cp.async.cg.shared.global [%0], [%1], 16;" :: "r"(dst_u32), "l"(src_ptr))
#define CP_COMMIT() asm volatile("cp.async.commit_group;" ::: "memory")
#define CP_WAIT0()  asm volatile("cp.async.wait_group 0;"  ::: "memory")

// ===========================================================================
// Kernel 1a: per-channel global average pool. grid (C_, B_), 128 threads.
// ===========================================================================
__global__ void __launch_bounds__(128) pool_kernel(const float* __restrict__ x) {
    const int c = blockIdx.x, b = blockIdx.y;
    const int tid = threadIdx.x;
    const float4* xc = (const float4*)(x + ((size_t)b*C_ + c)*NPIX);
    float s = 0.f;
    for (int i = tid; i < NPIX/4; i += 128) { float4 v = xc[i]; s += (v.x+v.y)+(v.z+v.w); }
    #pragma unroll
    for (int o = 16; o; o >>= 1) s += __shfl_xor_sync(0xffffffffu, s, o);
    __shared__ float ws[4];
    if ((tid & 31) == 0) ws[tid >> 5] = s;
    __syncthreads();
    if (tid == 0) g_pooled[b*C_ + c] = (ws[0]+ws[1]+ws[2]+ws[3]) * (1.0f/(float)NPIX);
}

// ===========================================================================
// Kernel 1b: MLP + softmax routing. grid B_, 64 threads.
// ===========================================================================
__global__ void __launch_bounds__(64) mlp_kernel(const float* __restrict__ rw1,
                                                 const float* __restrict__ rb1,
                                                 const float* __restrict__ rw2,
                                                 const float* __restrict__ rb2) {
    const int b = blockIdx.x, t = threadIdx.x;
    __shared__ float pl[C_];
    __shared__ float hid[HID_];
    __shared__ float logits[E_];
    for (int c = t; c < C_; c += 64) pl[c] = g_pooled[b*C_ + c];
    __syncthreads();
    {
        float s = rb1[t];
        const float* w = rw1 + t * C_;
        #pragma unroll 8
        for (int c = 0; c < C_; c++) s = fmaf(w[c], pl[c], s);
        hid[t] = fmaxf(s, 0.f);
    }
    __syncthreads();
    if (t < E_) {
        float s = rb2[t];
        const float* w = rw2 + t * HID_;
        #pragma unroll 8
        for (int h = 0; h < HID_; h++) s = fmaf(w[h], hid[h], s);
        logits[t] = s;
    }
    __syncthreads();
    if (t == 0) {
        float m = logits[0];
        #pragma unroll
        for (int e = 1; e < E_; e++) m = fmaxf(m, logits[e]);
        float ex[E_], sum = 0.f;
        #pragma unroll
        for (int e = 0; e < E_; e++) { ex[e] = expf(logits[e] - m); sum += ex[e]; }
        float inv = 1.0f / sum;
        #pragma unroll
        for (int e = 0; e < E_; e++) g_routing[b*E_ + e] = ex[e] * inv;
    }
}

// ===========================================================================
// Kernel 2: mix experts -> k-pair-interleaved tf32 A.  grid (2*NKT, B_).
// ===========================================================================
__global__ void __launch_bounds__(256) combine_kernel(const float* __restrict__ experts) {
    __shared__ float st[128*33];
    const int b  = blockIdx.y;
    const int bx = blockIdx.x;                 // tile_m*NKT + kt
    const int tile_m = bx / NKT;
    const int tid = threadIdx.x;

    const float r0 = g_routing[b*E_+0], r1 = g_routing[b*E_+1];
    const float r2 = g_routing[b*E_+2], r3 = g_routing[b*E_+3];

    // read 128 rows x 32 k (mixed, tf32-rounded) into smem (natural k order)
    const int row = tid >> 1, seg = tid & 1;
    const int kt = bx - tile_m*NKT;
    const size_t base = (size_t)(tile_m*128 + row)*KDIM + kt*32 + seg*16;
    #pragma unroll
    for (int q = 0; q < 4; q++) {
        float4 a = *(const float4*)(experts + base + 4*q);
        float4 c = *(const float4*)(experts + (size_t)WPERB   + base + 4*q);
        float4 d = *(const float4*)(experts + (size_t)2*WPERB + base + 4*q);
        float4 f = *(const float4*)(experts + (size_t)3*WPERB + base + 4*q);
        float* dst = st + row*33 + seg*16 + 4*q;
        dst[0] = __uint_as_float(f2tf32(r0*a.x + r1*c.x + r2*d.x + r3*f.x));
        dst[1] = __uint_as_float(f2tf32(r0*a.y + r1*c.y + r2*d.y + r3*f.y));
        dst[2] = __uint_as_float(f2tf32(r0*a.z + r1*c.z + r2*d.z + r3*f.z));
        dst[3] = __uint_as_float(f2tf32(r0*a.w + r1*c.w + r2*d.w + r3*f.w));
    }
    __syncthreads();

    // write interleaved: float4 u covers cols' 4c4..4c4+3 of row r
    uint4* gout = (uint4*)g_combined + (size_t)b*147456 + (size_t)bx*1024;
    #pragma unroll
    for (int w = 0; w < 4; w++) {
        const int u  = tid + 256*w;            // 0..1023
        const int r  = u >> 3, c4 = u & 7;
        const int ks = c4 >> 1;
        const float* s = st + r*33 + ks*8 + ((c4 & 1) ? 2 : 0);
        // even c4: j {0,4,1,5}; odd c4: j {2,6,3,7}  (offset by +2 handled above)
        gout[u] = make_uint4(__float_as_uint(s[0]), __float_as_uint(s[4]),
                             __float_as_uint(s[1]), __float_as_uint(s[5]));
    }
}

// ===========================================================================
// Kernel 3: TF32 mma.sync implicit-GEMM conv.
//   CTA 128(oc) x 128(px), 8 warps = 2(m) x 4(n), warp tile 64x32, 2 CTAs/SM.
//   Both operands k-pair interleaved in smem (PAD=40) -> LDS.64 fragments.
// ===========================================================================
__global__ void __launch_bounds__(256, 2) conv_mma_kernel(const float* __restrict__ x,
                                                          float* __restrict__ out) {
    extern __shared__ float sm[];
    int* ktab = (int*)(sm + KOFF);

    const int tid    = threadIdx.x;
    const int lane   = tid & 31;
    const int warp   = tid >> 5;
    const int nBase  = blockIdx.x * 128;
    const int tile_m = blockIdx.y;
    const int b      = blockIdx.z;

    const int g  = lane >> 2;
    const int tg = lane & 3;
    const int wm = warp >> 2;      // 0..1 (m)
    const int wn = warp & 3;       // 0..3 (n)

    // packed im2col table: (gmem offset << 4) | tap
    for (int k = tid; k < KDIM; k += 256) {
        int c = k / 9, rem = k - 9*c;
        int ky = rem / 3 - 1, kx = rem % 3 - 1;
        ktab[k] = ((c*NPIX + ky*WW + kx) << 4) | ((ky+1)*3 + (kx+1));
    }
    __syncthreads();

    const float* Asrc0 = g_combined + (size_t)b*WPERB + (size_t)(tile_m*NKT)*4096;
    const float* xb    = x + (size_t)b * C_ * NPIX;

    // B producer coords
    const int nl = tid & 127;
    const int kh = tid >> 7;
    const int n  = nBase + nl;
    const int ny = n / WW, nx = n - (n / WW) * WW;

    uint32_t vmask = 0;
    if (n < NPIX) {
        #pragma unroll
        for (int dy = -1; dy <= 1; dy++)
            #pragma unroll
            for (int dx = -1; dx <= 1; dx++)
                if ((unsigned)(ny+dy) < 56u && (unsigned)(nx+dx) < 56u)
                    vmask |= 1u << ((dy+1)*3 + (dx+1));
    }

    const uint32_t sb = (uint32_t)__cvta_generic_to_shared(sm);
    // per-warp fragment base addresses (bytes)
    const uint32_t aBase0 = sb + ((wm*64 + g)*PAD + 2*tg)*4u;
    const uint32_t bBase0 = sb + BOFF*4u + ((wn*32 + g)*PAD + 2*tg)*4u;
    const uint32_t stsB0  = sb + BOFF*4u + (nl*PAD + kh*16)*4u;

    uint32_t breg[16];

    #define ISSUE_A(kt_, s) do {                                                     \
        const float* _src = Asrc0 + (size_t)(kt_)*4096;                              \
        _Pragma("unroll")                                                            \
        for (int i = 0; i < 4; i++) {                                                \
            int idx = tid + i*256, r = idx >> 3, c16 = idx & 7;                      \
            CP_ASYNC16(sb + (s)*ASTG*4u + (uint32_t)(r*PAD + c16*4)*4u,              \
                       _src + idx*4);                                                \
        }                                                                            \
        CP_COMMIT();                                                                 \
    } while (0)

    #define LDG_B(kt_) do {                                                          \
        const int4* _kt4 = (const int4*)(ktab + (kt_)*BK + kh*16);                   \
        _Pragma("unroll")                                                            \
        for (int qq = 0; qq < 4; qq++) {                                             \
            int4 kv = _kt4[qq];                                                      \
            float f0=0.f,f1=0.f,f2=0.f,f3=0.f;                                       \
            if ((vmask >> (kv.x & 15)) & 1u) f0 = __ldg(xb + (kv.x >> 4) + n);       \
            if ((vmask >> (kv.y & 15)) & 1u) f1 = __ldg(xb + (kv.y >> 4) + n);       \
            if ((vmask >> (kv.z & 15)) & 1u) f2 = __ldg(xb + (kv.z >> 4) + n);       \
            if ((vmask >> (kv.w & 15)) & 1u) f3 = __ldg(xb + (kv.w >> 4) + n);       \
            breg[qq*4+0] = f2tf32(f0); breg[qq*4+1] = f2tf32(f1);                    \
            breg[qq*4+2] = f2tf32(f2); breg[qq*4+3] = f2tf32(f3);                    \
        }                                                                            \
    } while (0)

    // interleaved STS: positions {0..3}=j{0,4,1,5}, {4..7}=j{2,6,3,7}, +8 for ks+1
    #define STS_B(s) do {                                                            \
        const uint32_t _d = stsB0 + (s)*BSTG*4u;                                     \
        sts128(_d,      breg[0],  breg[4],  breg[1],  breg[5]);                     \
        sts128(_d + 16, breg[2],  breg[6],  breg[3],  breg[7]);                     \
        sts128(_d + 32, breg[8],  breg[12], breg[9],  breg[13]);                    \
        sts128(_d + 48, breg[10], breg[14], breg[11], breg[15]);                    \
    } while (0)

    // one ks step: 4 B LDS.64 + per-mi 2 A LDS.64 + 4 mma
    #define COMPUTE_KS(ks_, aB, bB) do {                                             \
        uint2 bf[4];                                                                 \
        _Pragma("unroll")                                                            \
        for (int ni = 0; ni < 4; ni++)                                               \
            bf[ni] = lds64((bB) + ni*1280u + (ks_)*32u);                             \
        _Pragma("unroll")                                                            \
        for (int mi = 0; mi < 4; mi++) {                                             \
            uint2 u = lds64((aB) + mi*2560u + (ks_)*32u);                            \
            uint2 v = lds64((aB) + mi*2560u + (ks_)*32u + 1280u);                    \
            _Pragma("unroll")                                                        \
            for (int ni = 0; ni < 4; ni++)                                           \
                mma_tf32s(acc[mi][ni], u.x, v.x, u.y, v.y, bf[ni].x, bf[ni].y);      \
        }                                                                            \
    } while (0)

    float acc[4][4][4];
    #pragma unroll
    for (int mi = 0; mi < 4; mi++)
        #pragma unroll
        for (int ni = 0; ni < 4; ni++)
            #pragma unroll
            for (int qq = 0; qq < 4; qq++) acc[mi][ni][qq] = 0.f;

    // ---- prologue ----
    ISSUE_A(0, 0);
    LDG_B(0);
    STS_B(0);
    CP_WAIT0();
    __syncthreads();

    for (int kt = 0; kt < NKT; kt++) {
        const int cur = kt & 1;
        const uint32_t aB = aBase0 + cur*(ASTG*4u);
        const uint32_t bB = bBase0 + cur*(BSTG*4u);

        if (kt + 1 < NKT) {
            ISSUE_A(kt + 1, cur ^ 1);
            LDG_B(kt + 1);
        }

        COMPUTE_KS(0, aB, bB);
        COMPUTE_KS(1, aB, bB);

        if (kt + 1 < NKT) STS_B(cur ^ 1);   // that buffer idle since barrier kt-1

        COMPUTE_KS(2, aB, bB);
        COMPUTE_KS(3, aB, bB);

        if (kt + 1 < NKT) {
            CP_WAIT0();
            __syncthreads();
        }
    }

    // ---- epilogue ----
    float* ob = out + (size_t)b * O_ * NPIX;
    #pragma unroll
    for (int mi = 0; mi < 4; mi++) {
        const int r0 = tile_m*128 + wm*64 + mi*16 + g;
        #pragma unroll
        for (int ni = 0; ni < 4; ni++) {
            const int cb = nBase + wn*32 + ni*8 + 2*tg;
            if (cb < NPIX) {
                *(float2*)(ob + (size_t)r0*NPIX + cb)     = make_float2(acc[mi][ni][0], acc[mi][ni][1]);
                *(float2*)(ob + (size_t)(r0+8)*NPIX + cb) = make_float2(acc[mi][ni][2], acc[mi][ni][3]);
            }
        }
    }
    #undef ISSUE_A
    #undef LDG_B
    #undef STS_B
    #undef COMPUTE_KS
}

// ===========================================================================
extern "C" void kernel_launch(void* const* d_in, const int* in_sizes, int n_in,
                              void* d_out, int out_size) {
    const float* x       = (const float*)d_in[0];
    const float* experts = (const float*)d_in[1];
    const float* rw1     = (const float*)d_in[2];
    const float* rb1     = (const float*)d_in[3];
    const float* rw2     = (const float*)d_in[4];
    const float* rb2     = (const float*)d_in[5];
    float* out           = (float*)d_out;

    static bool attr_set = false;
    if (!attr_set) {
        cudaFuncSetAttribute(conv_mma_kernel,
                             cudaFuncAttributeMaxDynamicSharedMemorySize, CONV_SMEM);
        attr_set = true;
    }

    pool_kernel<<<dim3(C_, B_), 128>>>(x);
    mlp_kernel<<<B_, 64>>>(rw1, rb1, rw2, rb2);
    combine_kernel<<<dim3(2*NKT, B_), 256>>>(experts);
    conv_mma_kernel<<<dim3(25, 2, B_), 256, CONV_SMEM>>>(x, out);
}

// round 11
// speedup vs baseline: 1.3120x; 1.1206x over previous
#include <cuda_runtime.h>
#include <cuda_bf16.h>
#include <stdint.h>
#include <math.h>

#define B_   32
#define C_   256
#define HH   56
#define WW   56
#define E_   4
#define O_   256
#define HID_ 64
#define NPIX 3136
#define KDIM 2304
#define WPERB (O_*KDIM)
#define BK   32
#define NKT  (KDIM/BK)                // 72 k-tiles
#define PADK 36                       // smem k-stride (floats)
#define PIMG 3364                     // 58*58 padded plane
#define ASTG (128*PADK)               // floats per A stage (4608)
#define BSTG (128*PADK)               // floats per B stage

// ---------------- device scratch (no runtime allocation) ----------------
__device__ float g_routing[B_*E_];
__device__ float g_pooled[B_*C_];
__device__ float g_combined[(size_t)B_*WPERB];        // tf32-rounded mixed weights
__device__ __align__(16) float g_xpad[(size_t)B_*C_*PIMG + 128]; // padded tf32 x (+slack)

// ---------------- helpers ----------------
__device__ __forceinline__ uint32_t f2tf32(float f) {
    uint32_t u;
    asm("cvt.rna.tf32.f32 %0, %1;" : "=r"(u) : "f"(f));
    return u;
}

__device__ __forceinline__ void mma_tf32(float* d, const uint32_t* a, const uint32_t* b) {
    asm volatile(
        "mma.sync.aligned.m16n8k8.row.col.f32.tf32.tf32.f32 "
        "{%0,%1,%2,%3}, {%4,%5,%6,%7}, {%8,%9}, {%0,%1,%2,%3};"
        : "+f"(d[0]), "+f"(d[1]), "+f"(d[2]), "+f"(d[3])
        : "r"(a[0]), "r"(a[1]), "r"(a[2]), "r"(a[3]), "r"(b[0]), "r"(b[1]));
}

#define CP_ASYNC16(dst_u32, src_ptr) \
    asm volatile("cp.async.cg.shared.global [%0], [%1], 16;" :: "r"(dst_u32), "l"(src_ptr))
#define CP_COMMIT() asm volatile("cp.async.commit_group;" ::: "memory")
#define CP_WAIT0()  asm volatile("cp.async.wait_group 0;"  ::: "memory")

// ===========================================================================
// Kernel 1a: fused zero-pad + tf32-round + global average pool.
//   grid (C_, B_), 128 threads. Writes g_xpad (tf32 values) and g_pooled.
// ===========================================================================
__global__ void __launch_bounds__(128) pad_pool_kernel(const float* __restrict__ x) {
    const int c = blockIdx.x, b = blockIdx.y;
    const int tid = threadIdx.x;
    const float* src = x + ((size_t)b*C_ + c)*NPIX;
    float* dst = g_xpad + ((size_t)b*C_ + c)*PIMG;

    float s = 0.f;
    for (int idx = tid; idx < PIMG; idx += 128) {
        const int py = idx / 58;
        const int px = idx - py*58;
        float v = 0.f;
        if ((unsigned)(py-1) < 56u && (unsigned)(px-1) < 56u) {
            v = src[(py-1)*WW + (px-1)];
            s += v;
        }
        dst[idx] = __uint_as_float(f2tf32(v));
    }
    #pragma unroll
    for (int o = 16; o; o >>= 1) s += __shfl_xor_sync(0xffffffffu, s, o);
    __shared__ float ws[4];
    if ((tid & 31) == 0) ws[tid >> 5] = s;
    __syncthreads();
    if (tid == 0) g_pooled[b*C_ + c] = (ws[0]+ws[1]+ws[2]+ws[3]) * (1.0f/(float)NPIX);
}

// ===========================================================================
// Kernel 1b: MLP + softmax routing. grid B_, 64 threads.
// ===========================================================================
__global__ void __launch_bounds__(64) mlp_kernel(const float* __restrict__ rw1,
                                                 const float* __restrict__ rb1,
                                                 const float* __restrict__ rw2,
                                                 const float* __restrict__ rb2) {
    const int b = blockIdx.x, t = threadIdx.x;
    __shared__ float pl[C_];
    __shared__ float hid[HID_];
    __shared__ float logits[E_];
    for (int c = t; c < C_; c += 64) pl[c] = g_pooled[b*C_ + c];
    __syncthreads();
    {
        float s = rb1[t];
        const float* w = rw1 + t * C_;
        #pragma unroll 8
        for (int c = 0; c < C_; c++) s = fmaf(w[c], pl[c], s);
        hid[t] = fmaxf(s, 0.f);
    }
    __syncthreads();
    if (t < E_) {
        float s = rb2[t];
        const float* w = rw2 + t * HID_;
        #pragma unroll 8
        for (int h = 0; h < HID_; h++) s = fmaf(w[h], hid[h], s);
        logits[t] = s;
    }
    __syncthreads();
    if (t == 0) {
        float m = logits[0];
        #pragma unroll
        for (int e = 1; e < E_; e++) m = fmaxf(m, logits[e]);
        float ex[E_], sum = 0.f;
        #pragma unroll
        for (int e = 0; e < E_; e++) { ex[e] = expf(logits[e] - m); sum += ex[e]; }
        float inv = 1.0f / sum;
        #pragma unroll
        for (int e = 0; e < E_; e++) g_routing[b*E_ + e] = ex[e] * inv;
    }
}

// ===========================================================================
// Kernel 2: mix experts -> per-sample weights (tf32-rounded fp32, flat layout).
// ===========================================================================
__global__ void __launch_bounds__(256) combine_kernel(const float* __restrict__ experts) {
    const int b = blockIdx.y;
    const int i = blockIdx.x * 256 + threadIdx.x;     // float4 index (exact grid)

    const float r0 = g_routing[b*E_+0], r1 = g_routing[b*E_+1];
    const float r2 = g_routing[b*E_+2], r3 = g_routing[b*E_+3];
    float4 a = ((const float4*)(experts + (size_t)0*WPERB))[i];
    float4 c = ((const float4*)(experts + (size_t)1*WPERB))[i];
    float4 d = ((const float4*)(experts + (size_t)2*WPERB))[i];
    float4 f = ((const float4*)(experts + (size_t)3*WPERB))[i];

    uint4 o;
    o.x = f2tf32(r0*a.x + r1*c.x + r2*d.x + r3*f.x);
    o.y = f2tf32(r0*a.y + r1*c.y + r2*d.y + r3*f.y);
    o.z = f2tf32(r0*a.z + r1*c.z + r2*d.z + r3*f.z);
    o.w = f2tf32(r0*a.w + r1*c.w + r2*d.w + r3*f.w);
    ((uint4*)g_combined)[(size_t)b*(WPERB/4) + i] = o;
}

// ===========================================================================
// Kernel 3: TF32 mma.sync implicit-GEMM conv (R6 skeleton, padded-x B path).
//   CTA 128(oc) x 128(px), 8 warps = 2(m) x 4(n), warp tile 64x32, 2 CTAs/SM.
//   A: cp.async double-buffered; B: LDG(g_xpad)->STS.128 (no mask, no cvt).
// ===========================================================================
__global__ void __launch_bounds__(256, 2) conv_mma_kernel(float* __restrict__ out) {
    extern __shared__ float sm[];
    float* As   = sm;                          // 2 * ASTG
    float* Bs   = sm + 2*ASTG;                 // 2 * BSTG
    int*   ktab = (int*)(sm + 2*ASTG + 2*BSTG);

    const int tid    = threadIdx.x;
    const int lane   = tid & 31;
    const int warp   = tid >> 5;
    const int nBase  = blockIdx.x * 128;
    const int tile_m = blockIdx.y;
    const int b      = blockIdx.z;

    const int g  = lane >> 2;      // 0..7
    const int tg = lane & 3;       // 0..3
    const int wm = warp >> 2;      // 0..1 (m)
    const int wn = warp & 3;       // 0..3 (n)

    // im2col table: gmem delta into padded planes
    for (int k = tid; k < KDIM; k += 256) {
        int c = k / 9, rem = k - 9*c;
        int ky = rem / 3 - 1, kx = rem % 3 - 1;
        ktab[k] = c*PIMG + ky*58 + kx;
    }
    __syncthreads();

    const float* Ab = g_combined + (size_t)b*WPERB + (size_t)(tile_m*128)*KDIM;

    // B producer: pixel nl, k-half kh; pointer pre-offset by padded pixel pos
    const int nl = tid & 127;
    const int kh = tid >> 7;
    const int n  = nBase + nl;
    const int ny = n / WW, nx = n - (n / WW) * WW;
    const float* xpb = g_xpad + (size_t)b*C_*PIMG + (ny+1)*58 + (nx+1);

    const uint32_t as_u32 = (uint32_t)__cvta_generic_to_shared(As);

    float breg[16];

    #define ISSUE_A(kt_, s) do {                                                     \
        const int _k0 = (kt_) * BK;                                                  \
        _Pragma("unroll")                                                            \
        for (int i = 0; i < 4; i++) {                                                \
            int idx = tid + i*256, row = idx >> 3, c4 = idx & 7;                     \
            uint32_t dst = as_u32 + (uint32_t)((s)*ASTG + row*PADK + c4*4)*4u;       \
            CP_ASYNC16(dst, Ab + (size_t)row*KDIM + _k0 + c4*4);                     \
        }                                                                            \
        CP_COMMIT();                                                                 \
    } while (0)

    #define LDG_B(kt_) do {                                                          \
        const int4* _kt4 = (const int4*)(ktab + (kt_)*BK + kh*16);                   \
        _Pragma("unroll")                                                            \
        for (int qq = 0; qq < 4; qq++) {                                             \
            int4 kv = _kt4[qq];                                                      \
            breg[qq*4+0] = __ldg(xpb + kv.x);                                        \
            breg[qq*4+1] = __ldg(xpb + kv.y);                                        \
            breg[qq*4+2] = __ldg(xpb + kv.z);                                        \
            breg[qq*4+3] = __ldg(xpb + kv.w);                                        \
        }                                                                            \
    } while (0)

    #define STS_B(s) do {                                                            \
        float4* _d = (float4*)(Bs + (s)*BSTG + nl*PADK + kh*16);                     \
        _Pragma("unroll")                                                            \
        for (int i = 0; i < 4; i++)                                                  \
            _d[i] = make_float4(breg[i*4], breg[i*4+1], breg[i*4+2], breg[i*4+3]);   \
    } while (0)

    #define COMPUTE_KS(ks) do {                                                      \
        const int kc = (ks)*8 + tg;                                                  \
        uint32_t afr[4][4];                                                          \
        _Pragma("unroll")                                                            \
        for (int mi = 0; mi < 4; mi++) {                                             \
            const uint32_t* p = Aw + mi*16*PADK + kc;                                \
            afr[mi][0] = p[0];                                                       \
            afr[mi][1] = p[8*PADK];                                                  \
            afr[mi][2] = p[4];                                                       \
            afr[mi][3] = p[8*PADK + 4];                                              \
        }                                                                            \
        uint32_t bfr[4][2];                                                          \
        _Pragma("unroll")                                                            \
        for (int ni = 0; ni < 4; ni++) {                                             \
            const uint32_t* q = Bw + ni*8*PADK + kc;                                 \
            bfr[ni][0] = q[0];                                                       \
            bfr[ni][1] = q[4];                                                       \
        }                                                                            \
        _Pragma("unroll")                                                            \
        for (int mi = 0; mi < 4; mi++)                                               \
            _Pragma("unroll")                                                        \
            for (int ni = 0; ni < 4; ni++)                                           \
                mma_tf32(acc[mi][ni], afr[mi], bfr[ni]);                             \
    } while (0)

    float acc[4][4][4];
    #pragma unroll
    for (int mi = 0; mi < 4; mi++)
        #pragma unroll
        for (int ni = 0; ni < 4; ni++)
            #pragma unroll
            for (int qq = 0; qq < 4; qq++) acc[mi][ni][qq] = 0.f;

    // ---- prologue ----
    ISSUE_A(0, 0);
    LDG_B(0);
    STS_B(0);
    CP_WAIT0();
    __syncthreads();

    for (int kt = 0; kt < NKT; kt++) {
        const int cur = kt & 1;
        if (kt + 1 < NKT) {
            ISSUE_A(kt + 1, cur ^ 1);
            LDG_B(kt + 1);
        }

        const uint32_t* Aw = (const uint32_t*)(As + cur*ASTG + (wm*64 + g)*PADK);
        const uint32_t* Bw = (const uint32_t*)(Bs + cur*BSTG + (wn*32 + g)*PADK);

        COMPUTE_KS(0);
        COMPUTE_KS(1);

        if (kt + 1 < NKT) STS_B(cur ^ 1);   // that buffer idle since barrier kt-1

        COMPUTE_KS(2);
        COMPUTE_KS(3);

        if (kt + 1 < NKT) {
            CP_WAIT0();
            __syncthreads();
        }
    }

    // ---- epilogue ----
    float* ob = out + (size_t)b * O_ * NPIX;
    #pragma unroll
    for (int mi = 0; mi < 4; mi++) {
        const int r0 = tile_m*128 + wm*64 + mi*16 + g;
        #pragma unroll
        for (int ni = 0; ni < 4; ni++) {
            const int cb = nBase + wn*32 + ni*8 + 2*tg;
            if (cb < NPIX) {
                *(float2*)(ob + (size_t)r0*NPIX + cb)     = make_float2(acc[mi][ni][0], acc[mi][ni][1]);
                *(float2*)(ob + (size_t)(r0+8)*NPIX + cb) = make_float2(acc[mi][ni][2], acc[mi][ni][3]);
            }
        }
    }
    #undef ISSUE_A
    #undef LDG_B
    #undef STS_B
    #undef COMPUTE_KS
}

#define CONV_SMEM ((2*ASTG + 2*BSTG + KDIM)*4)   // (9216+9216+2304)*4 = 82944 B

// ===========================================================================
extern "C" void kernel_launch(void* const* d_in, const int* in_sizes, int n_in,
                              void* d_out, int out_size) {
    const float* x       = (const float*)d_in[0];
    const float* experts = (const float*)d_in[1];
    const float* rw1     = (const float*)d_in[2];
    const float* rb1     = (const float*)d_in[3];
    const float* rw2     = (const float*)d_in[4];
    const float* rb2     = (const float*)d_in[5];
    float* out           = (float*)d_out;

    static bool attr_set = false;
    if (!attr_set) {
        cudaFuncSetAttribute(conv_mma_kernel,
                             cudaFuncAttributeMaxDynamicSharedMemorySize, CONV_SMEM);
        attr_set = true;
    }

    pad_pool_kernel<<<dim3(C_, B_), 128>>>(x);
    mlp_kernel<<<B_, 64>>>(rw1, rb1, rw2, rb2);
    combine_kernel<<<dim3(576, B_), 256>>>(experts);
    conv_mma_kernel<<<dim3(25, 2, B_), 256, CONV_SMEM>>>(out);
}